// round 5
// baseline (speedup 1.0000x reference)
#include <cuda_runtime.h>
#include <cuda_fp16.h>
#include <cstdint>
#include <cstddef>

// INT4 packed linear: y[64, 28672] = x[64, 8192] @ dequant(w_packed, scales) + bias
// Harness dtype canonicalization: fp16 tensors arrive/leave as float32 (lossless).
//   d_in[0] x      : float32 [64, 8192]   (fp16-representable values)
//   d_in[1] w      : int32   [4096, 28672] (byte payload: low nibble k even, high k odd)
//   d_in[2] scales : float32 [64, 28672]  (fp16-representable)
//   d_in[3] bias   : float32 [28672]
//   d_out          : float32 [64, 28672]
// Math replicates reference: fp16 dequant (w = (nib-8)*s in fp16), fp32 MMA accum,
// fp16 rounding of y, fp16 bias add, upcast to fp32.

#define K_DIM   8192
#define N_DIM   28672
#define M_DIM   64
#define WARPS   4
#define BN      128          // columns per CTA
#define BK      128          // one scale-group per stage
#define KSTEPS  (K_DIM / 16) // 512 k16 steps
#define NSTAGE  (K_DIM / BK) // 64 stages
#define XS_STRIDE 136        // halves per row (padded rows -> conflict-free ldmatrix)

// fp16 copy of x (scratch; __device__ globals are the allowed scratch mechanism)
__device__ __align__(16) __half g_xh[M_DIM * K_DIM];

__global__ void convert_x_kernel(const float* __restrict__ xf) {
    int i = (blockIdx.x * blockDim.x + threadIdx.x) * 4;
    float4 v = *reinterpret_cast<const float4*>(xf + i);
    __half2 h0 = __floats2half2_rn(v.x, v.y);
    __half2 h1 = __floats2half2_rn(v.z, v.w);
    *reinterpret_cast<__half2*>(&g_xh[i])     = h0;
    *reinterpret_cast<__half2*>(&g_xh[i + 2]) = h1;
}

__device__ __forceinline__ unsigned smem_u32(const void* p) {
    return (unsigned)__cvta_generic_to_shared(p);
}

__device__ __forceinline__ void ldsm_x4(unsigned& r0, unsigned& r1, unsigned& r2, unsigned& r3,
                                        unsigned addr) {
    asm volatile("ldmatrix.sync.aligned.m8n8.x4.shared.b16 {%0,%1,%2,%3}, [%4];\n"
                 : "=r"(r0), "=r"(r1), "=r"(r2), "=r"(r3)
                 : "r"(addr));
}

__device__ __forceinline__ void mma_16816(float& c0, float& c1, float& c2, float& c3,
                                          unsigned a0, unsigned a1, unsigned a2, unsigned a3,
                                          unsigned b0, unsigned b1) {
    asm volatile("mma.sync.aligned.m16n8k16.row.col.f32.f16.f16.f32 "
                 "{%0,%1,%2,%3}, {%4,%5,%6,%7}, {%8,%9}, {%0,%1,%2,%3};\n"
                 : "+f"(c0), "+f"(c1), "+f"(c2), "+f"(c3)
                 : "r"(a0), "r"(a1), "r"(a2), "r"(a3), "r"(b0), "r"(b1));
}

__device__ __forceinline__ void cp_async16(unsigned saddr, const void* gaddr) {
    asm volatile("cp.async.cg.shared.global [%0], [%1], 16;\n"
                 :: "r"(saddr), "l"(gaddr));
}

// q int32 in [0,256): build fp16x2 {1024+lo, 1024+hi}, subtract 1032 (exact),
// multiply by scale (single fp16 rounding == reference dequant).
__device__ __forceinline__ unsigned dequant(unsigned q, __half2 s2) {
    unsigned t = ((q | (q << 12)) | 0x64006400u) & 0x640F640Fu;
    __half2 th = *reinterpret_cast<__half2*>(&t);
    const unsigned offc = 0x64086408u;  // half2 {1032, 1032}
    __half2 off = *reinterpret_cast<const __half2*>(&offc);
    __half2 w = __hmul2(__hsub2(th, off), s2);
    return *reinterpret_cast<unsigned*>(&w);
}

__global__ __launch_bounds__(128, 2)
void int4_linear_kernel(const int* __restrict__ w,
                        const float* __restrict__ scales,
                        const float* __restrict__ bias,
                        float* __restrict__ out) {
    __shared__ __half xs[2][M_DIM * XS_STRIDE];

    const int tid  = threadIdx.x;
    const int lane = tid & 31;
    const int warp = tid >> 5;
    const int r    = lane & 3;    // kh sub-row within B fragment
    const int c    = lane >> 2;   // n sub-col within n8 tile
    const int nwarp = blockIdx.x * BN + warp * 32;
    const int col   = nwarp + c;

    float acc[4][4][4];
#pragma unroll
    for (int mi = 0; mi < 4; ++mi)
#pragma unroll
        for (int j = 0; j < 4; ++j)
#pragma unroll
            for (int f = 0; f < 4; ++f) acc[mi][j][f] = 0.0f;

    // x stage copy: 64 rows x 128 halves = 1024 x 16B chunks, 8 per thread
    auto copy_stage = [&](int g, int buf) {
#pragma unroll
        for (int i = 0; i < 8; ++i) {
            int idx = tid + i * 128;
            int row = idx >> 4;
            int cc  = idx & 15;
            const __half* gp = g_xh + (size_t)row * K_DIM + (size_t)g * BK + cc * 8;
            unsigned sp = smem_u32(&xs[buf][row * XS_STRIDE + cc * 8]);
            cp_async16(sp, gp);
        }
        asm volatile("cp.async.commit_group;\n");
    };

    // weight loads: directly into B-fragment layout
    const int* wbase = w + (size_t)r * N_DIM + col;
    auto load_w = [&](int ks, unsigned q0[4], unsigned q1[4]) {
        const int* p = wbase + (size_t)(ks * 8) * N_DIM;
#pragma unroll
        for (int j = 0; j < 4; ++j) {
            q0[j] = (unsigned)__ldg(p + j * 8);
            q1[j] = (unsigned)__ldg(p + (size_t)4 * N_DIM + j * 8);
        }
    };

    const unsigned a_lane_off =
        (unsigned)(((lane & 15) * XS_STRIDE + (lane >> 4) * 8) * sizeof(__half));
    const unsigned xs_base[2] = { smem_u32(&xs[0][0]), smem_u32(&xs[1][0]) };

    // prologue: prefetch two x stages + first weight step
    copy_stage(0, 0);
    copy_stage(1, 1);
    unsigned q0[4], q1[4], p0[4], p1[4];
    load_w(0, q0, q1);

    for (int g = 0; g < NSTAGE; ++g) {
        if (g < NSTAGE - 1) asm volatile("cp.async.wait_group 1;\n");
        else                asm volatile("cp.async.wait_group 0;\n");
        __syncthreads();

        // per-group scales (group == stage since BK == 128); f32 -> fp16 is exact
        __half2 s2[4];
#pragma unroll
        for (int j = 0; j < 4; ++j) {
            float s = __ldg(scales + (size_t)g * N_DIM + col + j * 8);
            s2[j] = __half2half2(__float2half_rn(s));
        }

        const unsigned sbase = xs_base[g & 1];

#pragma unroll
        for (int t = 0; t < 8; ++t) {
            int ks  = g * 8 + t;
            int ksn = ks + 1;
            if (ksn >= KSTEPS) ksn = KSTEPS - 1;  // harmless redundant tail reload
            load_w(ksn, p0, p1);                   // prefetch next step's weights

            unsigned a[4][4];
#pragma unroll
            for (int mi = 0; mi < 4; ++mi) {
                unsigned addr = sbase + a_lane_off +
                                (unsigned)((mi * 16 * XS_STRIDE + t * 16) * sizeof(__half));
                ldsm_x4(a[mi][0], a[mi][1], a[mi][2], a[mi][3], addr);
            }

#pragma unroll
            for (int j = 0; j < 4; ++j) {
                unsigned b0 = dequant(q0[j], s2[j]);
                unsigned b1 = dequant(q1[j], s2[j]);
#pragma unroll
                for (int mi = 0; mi < 4; ++mi)
                    mma_16816(acc[mi][j][0], acc[mi][j][1], acc[mi][j][2], acc[mi][j][3],
                              a[mi][0], a[mi][1], a[mi][2], a[mi][3], b0, b1);
            }
#pragma unroll
            for (int j = 0; j < 4; ++j) { q0[j] = p0[j]; q1[j] = p1[j]; }
        }

        __syncthreads();                        // all warps done with buf g&1
        if (g + 2 < NSTAGE) copy_stage(g + 2, g & 1);
    }

    // epilogue: fp32 acc -> fp16 round, + fp16 bias (matches reference), upcast -> f32 store
#pragma unroll
    for (int mi = 0; mi < 4; ++mi) {
        int m0 = mi * 16 + (lane >> 2);
#pragma unroll
        for (int j = 0; j < 4; ++j) {
            int n = nwarp + j * 8 + 2 * (lane & 3);
            float2 bf = *reinterpret_cast<const float2*>(bias + n);
            __half2 bb = __floats2half2_rn(bf.x, bf.y);  // exact (fp16-representable)

            __half2 v0 = __halves2half2(__float2half_rn(acc[mi][j][0]),
                                        __float2half_rn(acc[mi][j][1]));
            v0 = __hadd2(v0, bb);
            float2 o0 = { __half2float(__low2half(v0)), __half2float(__high2half(v0)) };
            *reinterpret_cast<float2*>(out + (size_t)m0 * N_DIM + n) = o0;

            __half2 v1 = __halves2half2(__float2half_rn(acc[mi][j][2]),
                                        __float2half_rn(acc[mi][j][3]));
            v1 = __hadd2(v1, bb);
            float2 o1 = { __half2float(__low2half(v1)), __half2float(__high2half(v1)) };
            *reinterpret_cast<float2*>(out + (size_t)(m0 + 8) * N_DIM + n) = o1;
        }
    }
}

extern "C" void kernel_launch(void* const* d_in, const int* in_sizes, int n_in,
                              void* d_out, int out_size) {
    const float* x      = (const float*)d_in[0];
    const int*   w      = (const int*)d_in[1];
    const float* scales = (const float*)d_in[2];
    const float* bias   = (const float*)d_in[3];
    float*       out    = (float*)d_out;

    // 1) x: f32 -> fp16 scratch (lossless; values are fp16-representable)
    convert_x_kernel<<<(M_DIM * K_DIM / 4 + 255) / 256, 256>>>(x);

    // 2) main GEMM
    dim3 grid(N_DIM / BN);   // 224 CTAs
    dim3 block(WARPS * 32);  // 128 threads
    int4_linear_kernel<<<grid, block>>>(w, scales, bias, out);
}

// round 6
// speedup vs baseline: 1.4532x; 1.4532x over previous
#include <cuda_runtime.h>
#include <cuda_fp16.h>
#include <cstdint>
#include <cstddef>

// INT4 packed linear: y[64, 28672] = x[64, 8192] @ dequant(w_packed, scales) + bias
// Harness canonicalizes fp16 tensors to float32 (lossless): x/scales/bias/out are f32.
// Math replicates reference: fp16 dequant ((nib-8)*s in fp16), fp32 MMA accum,
// fp16 rounding of y, fp16 bias add, upcast to f32 for the store.

#define K_DIM   8192
#define N_DIM   28672
#define M_DIM   64
#define BN      64           // columns per CTA (4 warps x 16 cols)
#define BK      128          // one scale-group per stage
#define KSTEPS  (K_DIM / 16) // 512 k16 steps
#define NSTAGE  (K_DIM / BK) // 64 stages
#define XS_STRIDE 136        // halves per row (padded -> conflict-free ldmatrix)

// fp16 copy of x (scratch via __device__ global)
__device__ __align__(16) __half g_xh[M_DIM * K_DIM];

__global__ void convert_x_kernel(const float* __restrict__ xf) {
    int i = (blockIdx.x * blockDim.x + threadIdx.x) * 4;
    float4 v = *reinterpret_cast<const float4*>(xf + i);
    *reinterpret_cast<__half2*>(&g_xh[i])     = __floats2half2_rn(v.x, v.y);
    *reinterpret_cast<__half2*>(&g_xh[i + 2]) = __floats2half2_rn(v.z, v.w);
}

__device__ __forceinline__ unsigned smem_u32(const void* p) {
    return (unsigned)__cvta_generic_to_shared(p);
}

__device__ __forceinline__ void ldsm_x4(unsigned& r0, unsigned& r1, unsigned& r2, unsigned& r3,
                                        unsigned addr) {
    asm volatile("ldmatrix.sync.aligned.m8n8.x4.shared.b16 {%0,%1,%2,%3}, [%4];\n"
                 : "=r"(r0), "=r"(r1), "=r"(r2), "=r"(r3)
                 : "r"(addr));
}

__device__ __forceinline__ void mma_16816(float& c0, float& c1, float& c2, float& c3,
                                          unsigned a0, unsigned a1, unsigned a2, unsigned a3,
                                          unsigned b0, unsigned b1) {
    asm volatile("mma.sync.aligned.m16n8k16.row.col.f32.f16.f16.f32 "
                 "{%0,%1,%2,%3}, {%4,%5,%6,%7}, {%8,%9}, {%0,%1,%2,%3};\n"
                 : "+f"(c0), "+f"(c1), "+f"(c2), "+f"(c3)
                 : "r"(a0), "r"(a1), "r"(a2), "r"(a3), "r"(b0), "r"(b1));
}

__device__ __forceinline__ void cp_async16(unsigned saddr, const void* gaddr) {
    asm volatile("cp.async.cg.shared.global [%0], [%1], 16;\n"
                 :: "r"(saddr), "l"(gaddr));
}

// q in [0,256): fp16x2 {1024+lo, 1024+hi} - 1032 (exact), * scale (one fp16 rounding).
__device__ __forceinline__ unsigned dequant(unsigned q, __half2 s2) {
    unsigned t = ((q | (q << 12)) | 0x64006400u) & 0x640F640Fu;
    __half2 th = *reinterpret_cast<__half2*>(&t);
    const unsigned offc = 0x64086408u;  // half2 {1032, 1032}
    __half2 off = *reinterpret_cast<const __half2*>(&offc);
    __half2 wv = __hmul2(__hsub2(th, off), s2);
    return *reinterpret_cast<unsigned*>(&wv);
}

__global__ __launch_bounds__(128, 3)
void int4_linear_kernel(const int* __restrict__ w,
                        const float* __restrict__ scales,
                        const float* __restrict__ bias,
                        float* __restrict__ out) {
    __shared__ __half xs[2][M_DIM * XS_STRIDE];

    const int tid  = threadIdx.x;
    const int lane = tid & 31;
    const int warp = tid >> 5;
    const int r    = lane & 3;    // kh sub-row within B fragment
    const int c    = lane >> 2;   // n sub-col within n8 tile
    const int nwarp = blockIdx.x * BN + warp * 16;  // 16 cols per warp
    const int col   = nwarp + c;

    // accumulators: [m-subtile 0..3][n-subtile 0..1][frag 0..3]  (32 regs)
    float acc[4][2][4];
#pragma unroll
    for (int mi = 0; mi < 4; ++mi)
#pragma unroll
        for (int j = 0; j < 2; ++j)
#pragma unroll
            for (int f = 0; f < 4; ++f) acc[mi][j][f] = 0.0f;

    // x stage copy: 64 rows x 128 halves = 1024 x 16B chunks, 8 per thread
    auto copy_stage = [&](int g, int buf) {
#pragma unroll
        for (int i = 0; i < 8; ++i) {
            int idx = tid + i * 128;
            int row = idx >> 4;
            int cc  = idx & 15;
            const __half* gp = g_xh + (size_t)row * K_DIM + (size_t)g * BK + cc * 8;
            unsigned sp = smem_u32(&xs[buf][row * XS_STRIDE + cc * 8]);
            cp_async16(sp, gp);
        }
        asm volatile("cp.async.commit_group;\n");
    };

    // weight loads, direct into B-fragment layout: slot = {q0[2], q1[2]}
    const int* wbase = w + (size_t)r * N_DIM + col;
    auto load_w = [&](int ks, unsigned q[4]) {
        const int* p = wbase + (size_t)(ks * 8) * N_DIM;
#pragma unroll
        for (int j = 0; j < 2; ++j) {
            q[j]     = (unsigned)__ldg(p + j * 8);                      // rows r..r+3 (k 0..7)
            q[2 + j] = (unsigned)__ldg(p + (size_t)4 * N_DIM + j * 8);  // rows r+4.. (k 8..15)
        }
    };

    const unsigned a_lane_off =
        (unsigned)(((lane & 15) * XS_STRIDE + (lane >> 4) * 8) * sizeof(__half));
    const unsigned xs_base[2] = { smem_u32(&xs[0][0]), smem_u32(&xs[1][0]) };

    // ---- prologue: x double-buffer, 3-deep weight queue, stage-0 scales
    copy_stage(0, 0);
    copy_stage(1, 1);
    unsigned qa[4], qb[4], qc[4], qd[4];
    load_w(0, qa);
    load_w(1, qb);
    load_w(2, qc);

    float sraw[2];
#pragma unroll
    for (int j = 0; j < 2; ++j)
        sraw[j] = __ldg(scales + col + j * 8);   // stage 0

    for (int g = 0; g < NSTAGE; ++g) {
        if (g < NSTAGE - 1) asm volatile("cp.async.wait_group 1;\n");
        else                asm volatile("cp.async.wait_group 0;\n");
        __syncthreads();

        // current stage scales (f32 -> fp16 exact), prefetch next stage's
        __half2 s2[2];
#pragma unroll
        for (int j = 0; j < 2; ++j)
            s2[j] = __half2half2(__float2half_rn(sraw[j]));
        {
            int gn = (g + 1 < NSTAGE) ? g + 1 : g;
#pragma unroll
            for (int j = 0; j < 2; ++j)
                sraw[j] = __ldg(scales + (size_t)gn * N_DIM + col + j * 8);
        }

        const unsigned sbase = xs_base[g & 1];

#pragma unroll
        for (int t = 0; t < 8; ++t) {
            int ks  = g * 8 + t;
            int ksn = ks + 3;
            if (ksn >= KSTEPS) ksn = KSTEPS - 1;   // harmless redundant tail reload
            load_w(ksn, qd);                        // fill queue tail

            // A fragments: 4 m16k16 tiles from SMEM
            unsigned a[4][4];
#pragma unroll
            for (int mi = 0; mi < 4; ++mi) {
                unsigned addr = sbase + a_lane_off +
                                (unsigned)((mi * 16 * XS_STRIDE + t * 16) * sizeof(__half));
                ldsm_x4(a[mi][0], a[mi][1], a[mi][2], a[mi][3], addr);
            }

            // dequant + mma (consume queue head qa)
#pragma unroll
            for (int j = 0; j < 2; ++j) {
                unsigned b0 = dequant(qa[j],     s2[j]);
                unsigned b1 = dequant(qa[2 + j], s2[j]);
#pragma unroll
                for (int mi = 0; mi < 4; ++mi)
                    mma_16816(acc[mi][j][0], acc[mi][j][1], acc[mi][j][2], acc[mi][j][3],
                              a[mi][0], a[mi][1], a[mi][2], a[mi][3], b0, b1);
            }

            // rotate queue (register renaming under full unroll)
#pragma unroll
            for (int i = 0; i < 4; ++i) { qa[i] = qb[i]; qb[i] = qc[i]; qc[i] = qd[i]; }
        }

        __syncthreads();
        if (g + 2 < NSTAGE) copy_stage(g + 2, g & 1);
    }

    // epilogue: fp32 acc -> fp16 round, + fp16 bias, upcast -> f32 store
#pragma unroll
    for (int mi = 0; mi < 4; ++mi) {
        int m0 = mi * 16 + (lane >> 2);
#pragma unroll
        for (int j = 0; j < 2; ++j) {
            int n = nwarp + j * 8 + 2 * (lane & 3);
            float2 bf = *reinterpret_cast<const float2*>(bias + n);
            __half2 bb = __floats2half2_rn(bf.x, bf.y);  // exact

            __half2 v0 = __halves2half2(__float2half_rn(acc[mi][j][0]),
                                        __float2half_rn(acc[mi][j][1]));
            v0 = __hadd2(v0, bb);
            float2 o0 = { __half2float(__low2half(v0)), __half2float(__high2half(v0)) };
            *reinterpret_cast<float2*>(out + (size_t)m0 * N_DIM + n) = o0;

            __half2 v1 = __halves2half2(__float2half_rn(acc[mi][j][2]),
                                        __float2half_rn(acc[mi][j][3]));
            v1 = __hadd2(v1, bb);
            float2 o1 = { __half2float(__low2half(v1)), __half2float(__high2half(v1)) };
            *reinterpret_cast<float2*>(out + (size_t)(m0 + 8) * N_DIM + n) = o1;
        }
    }
}

extern "C" void kernel_launch(void* const* d_in, const int* in_sizes, int n_in,
                              void* d_out, int out_size) {
    const float* x      = (const float*)d_in[0];
    const int*   w      = (const int*)d_in[1];
    const float* scales = (const float*)d_in[2];
    const float* bias   = (const float*)d_in[3];
    float*       out    = (float*)d_out;

    convert_x_kernel<<<(M_DIM * K_DIM / 4 + 255) / 256, 256>>>(x);

    dim3 grid(N_DIM / BN);   // 448 CTAs (~3 per SM)
    dim3 block(128);         // 4 warps x 16 columns
    int4_linear_kernel<<<grid, block>>>(w, scales, bias, out);
}

// round 8
// speedup vs baseline: 1.6389x; 1.1278x over previous
#include <cuda_runtime.h>
#include <cuda_fp16.h>
#include <cstdint>
#include <cstddef>

// INT4 packed linear: y[64, 28672] = x[64, 8192] @ dequant(w_packed, scales) + bias
// Harness canonicalizes fp16 tensors to float32 (lossless): x/scales/bias/out are f32.
// Math replicates reference: fp16 dequant ((nib-8)*s in fp16), fp32 MMA accum,
// fp16 rounding of y, fp16 bias add, upcast to f32 for the store.

#define K_DIM   8192
#define N_DIM   28672
#define M_DIM   64
#define BN      64            // columns per CTA (4 warps x 16 cols)
#define BK      64            // k per stage (32 packed rows); scale-group = 2 stages
#define NSTAGE  (K_DIM / BK)  // 128 stages
#define XS_STRIDE 72          // halves per x row: 144B = 9*16 (aligned) + conflict-free
#define WS_STRIDE 72          // ints per w row: 288B (aligned) + conflict-free LDS frags

// fp16 copy of x (scratch via __device__ global)
__device__ __align__(16) __half g_xh[M_DIM * K_DIM];

__global__ void convert_x_kernel(const float* __restrict__ xf) {
    int i = (blockIdx.x * blockDim.x + threadIdx.x) * 4;
    float4 v = *reinterpret_cast<const float4*>(xf + i);
    *reinterpret_cast<__half2*>(&g_xh[i])     = __floats2half2_rn(v.x, v.y);
    *reinterpret_cast<__half2*>(&g_xh[i + 2]) = __floats2half2_rn(v.z, v.w);
}

__device__ __forceinline__ unsigned smem_u32(const void* p) {
    return (unsigned)__cvta_generic_to_shared(p);
}

__device__ __forceinline__ void ldsm_x4(unsigned& r0, unsigned& r1, unsigned& r2, unsigned& r3,
                                        unsigned addr) {
    asm volatile("ldmatrix.sync.aligned.m8n8.x4.shared.b16 {%0,%1,%2,%3}, [%4];\n"
                 : "=r"(r0), "=r"(r1), "=r"(r2), "=r"(r3)
                 : "r"(addr));
}

__device__ __forceinline__ void mma_16816(float& c0, float& c1, float& c2, float& c3,
                                          unsigned a0, unsigned a1, unsigned a2, unsigned a3,
                                          unsigned b0, unsigned b1) {
    asm volatile("mma.sync.aligned.m16n8k16.row.col.f32.f16.f16.f32 "
                 "{%0,%1,%2,%3}, {%4,%5,%6,%7}, {%8,%9}, {%0,%1,%2,%3};\n"
                 : "+f"(c0), "+f"(c1), "+f"(c2), "+f"(c3)
                 : "r"(a0), "r"(a1), "r"(a2), "r"(a3), "r"(b0), "r"(b1));
}

__device__ __forceinline__ void cp_async16(unsigned saddr, const void* gaddr) {
    asm volatile("cp.async.cg.shared.global [%0], [%1], 16;\n"
                 :: "r"(saddr), "l"(gaddr));
}

// q in [0,256): fp16x2 {1024+lo, 1024+hi} - 1032 (exact), * scale (one fp16 rounding).
__device__ __forceinline__ unsigned dequant(unsigned q, __half2 s2) {
    unsigned t = ((q | (q << 12)) | 0x64006400u) & 0x640F640Fu;
    __half2 th = *reinterpret_cast<__half2*>(&t);
    const unsigned offc = 0x64086408u;  // half2 {1032, 1032}
    __half2 off = *reinterpret_cast<const __half2*>(&offc);
    __half2 wv = __hmul2(__hsub2(th, off), s2);
    return *reinterpret_cast<unsigned*>(&wv);
}

__global__ __launch_bounds__(128, 3)
void int4_linear_kernel(const int* __restrict__ w,
                        const float* __restrict__ scales,
                        const float* __restrict__ bias,
                        float* __restrict__ out) {
    __shared__ __half xs[2][M_DIM * XS_STRIDE];     // 2 x 9216 B
    __shared__ int    ws[2][(BK / 2) * WS_STRIDE];  // 2 x 9216 B

    const int tid  = threadIdx.x;
    const int lane = tid & 31;
    const int warp = tid >> 5;
    const int r    = lane & 3;    // kh sub-row within B fragment
    const int c    = lane >> 2;   // n sub-col within n8 tile
    const int nwarp = blockIdx.x * BN + warp * 16;  // 16 cols per warp
    const int col   = nwarp + c;
    const int wc    = warp * 16 + c;  // column word index inside CTA tile

    // accumulators: [m-subtile 0..3][n-subtile 0..1][frag 0..3]
    float acc[4][2][4];
#pragma unroll
    for (int mi = 0; mi < 4; ++mi)
#pragma unroll
        for (int j = 0; j < 2; ++j)
#pragma unroll
            for (int f = 0; f < 4; ++f) acc[mi][j][f] = 0.0f;

    const int* wsrc = w + (size_t)blockIdx.x * BN;

    // stage copy: x tile (64 rows x 64 halves) + w tile (32 rows x 64 ints), 1 group
    auto copy_stage = [&](int g, int buf) {
#pragma unroll
        for (int i = 0; i < 4; ++i) {           // x: 512 chunks of 16B
            int idx = tid + i * 128;
            int row = idx >> 3;
            int cc  = idx & 7;
            const __half* gp = g_xh + (size_t)row * K_DIM + (size_t)g * BK + cc * 8;
            cp_async16(smem_u32(&xs[buf][row * XS_STRIDE + cc * 8]), gp);
        }
#pragma unroll
        for (int i = 0; i < 4; ++i) {           // w: 512 chunks of 16B
            int idx = tid + i * 128;
            int row = idx >> 4;
            int cc  = idx & 15;
            const int* gp = wsrc + (size_t)(g * (BK / 2) + row) * N_DIM + cc * 4;
            cp_async16(smem_u32(&ws[buf][row * WS_STRIDE + cc * 4]), gp);
        }
        asm volatile("cp.async.commit_group;\n");
    };

    // fragment read from staged weights: step t covers packed rows t*8 .. t*8+7
    auto lds_w = [&](const int* wsb, int t, unsigned q[4]) {
        const int* p = wsb + (t * 8 + r) * WS_STRIDE + wc;
#pragma unroll
        for (int j = 0; j < 2; ++j) {
            q[j]     = (unsigned)p[j * 8];
            q[2 + j] = (unsigned)p[4 * WS_STRIDE + j * 8];
        }
    };

    const unsigned a_lane_off =
        (unsigned)(((lane & 15) * XS_STRIDE + (lane >> 4) * 8) * sizeof(__half));
    const unsigned xs_base[2] = { smem_u32(&xs[0][0]), smem_u32(&xs[1][0]) };

    // prologue
    copy_stage(0, 0);
    copy_stage(1, 1);

    float sraw[2];
#pragma unroll
    for (int j = 0; j < 2; ++j)
        sraw[j] = __ldg(scales + col + j * 8);   // group 0

    __half2 s2[2];

    for (int g = 0; g < NSTAGE; ++g) {
        if (g < NSTAGE - 1) asm volatile("cp.async.wait_group 1;\n");
        else                asm volatile("cp.async.wait_group 0;\n");
        __syncthreads();

        if ((g & 1) == 0) {
            // new scale group: convert current, prefetch next group's raw scales
#pragma unroll
            for (int j = 0; j < 2; ++j)
                s2[j] = __half2half2(__float2half_rn(sraw[j]));
            int gn = (g >> 1) + 1;
            if (gn > 63) gn = 63;
#pragma unroll
            for (int j = 0; j < 2; ++j)
                sraw[j] = __ldg(scales + (size_t)gn * N_DIM + col + j * 8);
        }

        const int buf = g & 1;
        const unsigned sbase = xs_base[buf];
        const int* wsb = &ws[buf][0];

        unsigned qc[4], qn[4];
        lds_w(wsb, 0, qc);

#pragma unroll
        for (int t = 0; t < 4; ++t) {
            if (t < 3) lds_w(wsb, t + 1, qn);   // prefetch next step's frags

            unsigned a[4][4];
#pragma unroll
            for (int mi = 0; mi < 4; ++mi) {
                unsigned addr = sbase + a_lane_off +
                                (unsigned)((mi * 16 * XS_STRIDE + t * 16) * sizeof(__half));
                ldsm_x4(a[mi][0], a[mi][1], a[mi][2], a[mi][3], addr);
            }

#pragma unroll
            for (int j = 0; j < 2; ++j) {
                unsigned b0 = dequant(qc[j],     s2[j]);
                unsigned b1 = dequant(qc[2 + j], s2[j]);
#pragma unroll
                for (int mi = 0; mi < 4; ++mi)
                    mma_16816(acc[mi][j][0], acc[mi][j][1], acc[mi][j][2], acc[mi][j][3],
                              a[mi][0], a[mi][1], a[mi][2], a[mi][3], b0, b1);
            }
#pragma unroll
            for (int i = 0; i < 4; ++i) qc[i] = qn[i];
        }

        __syncthreads();                 // all warps done reading buf
        if (g + 2 < NSTAGE) copy_stage(g + 2, buf);
    }

    // epilogue: fp32 acc -> fp16 round, + fp16 bias, upcast -> f32 store
#pragma unroll
    for (int mi = 0; mi < 4; ++mi) {
        int m0 = mi * 16 + (lane >> 2);
#pragma unroll
        for (int j = 0; j < 2; ++j) {
            int n = nwarp + j * 8 + 2 * (lane & 3);
            float2 bf = *reinterpret_cast<const float2*>(bias + n);
            __half2 bb = __floats2half2_rn(bf.x, bf.y);  // exact

            __half2 v0 = __halves2half2(__float2half_rn(acc[mi][j][0]),
                                        __float2half_rn(acc[mi][j][1]));
            v0 = __hadd2(v0, bb);
            float2 o0 = { __half2float(__low2half(v0)), __half2float(__high2half(v0)) };
            *reinterpret_cast<float2*>(out + (size_t)m0 * N_DIM + n) = o0;

            __half2 v1 = __halves2half2(__float2half_rn(acc[mi][j][2]),
                                        __float2half_rn(acc[mi][j][3]));
            v1 = __hadd2(v1, bb);
            float2 o1 = { __half2float(__low2half(v1)), __half2float(__high2half(v1)) };
            *reinterpret_cast<float2*>(out + (size_t)(m0 + 8) * N_DIM + n) = o1;
        }
    }
}

extern "C" void kernel_launch(void* const* d_in, const int* in_sizes, int n_in,
                              void* d_out, int out_size) {
    const float* x      = (const float*)d_in[0];
    const int*   w      = (const int*)d_in[1];
    const float* scales = (const float*)d_in[2];
    const float* bias   = (const float*)d_in[3];
    float*       out    = (float*)d_out;

    convert_x_kernel<<<(M_DIM * K_DIM / 4 + 255) / 256, 256>>>(x);

    dim3 grid(N_DIM / BN);   // 448 CTAs (~3 per SM, balanced)
    dim3 block(128);         // 4 warps x 16 columns
    int4_linear_kernel<<<grid, block>>>(w, scales, bias, out);
}

// round 9
// speedup vs baseline: 1.8499x; 1.1287x over previous
#include <cuda_runtime.h>
#include <cuda_fp16.h>
#include <cstdint>
#include <cstddef>

// INT4 packed linear: y[64, 28672] = x[64, 8192] @ dequant(w_packed, scales) + bias
// Harness canonicalizes fp16 tensors to float32 (lossless): x/scales/bias/out are f32.
// Math replicates reference: fp16 dequant ((nib-8)*s in fp16), fp32 MMA accum,
// fp16 rounding of y, fp16 bias add, upcast to f32 for the store.
//
// R9: 3-buffer cp.async pipeline (2 stages in flight), 1 barrier/stage,
//     zero-pad XOR-swizzled SMEM (fits 48KB static exactly).

#define K_DIM   8192
#define N_DIM   28672
#define M_DIM   64
#define BN      64            // columns per CTA (4 warps x 16 cols)
#define BK      64            // k per stage (32 packed rows); scale-group = 2 stages
#define NSTAGE  (K_DIM / BK)  // 128 stages
#define NBUF    3

// fp16 copy of x (scratch via __device__ global)
__device__ __align__(16) __half g_xh[M_DIM * K_DIM];

__global__ void convert_x_kernel(const float* __restrict__ xf) {
    int i = (blockIdx.x * blockDim.x + threadIdx.x) * 4;
    float4 v = *reinterpret_cast<const float4*>(xf + i);
    *reinterpret_cast<__half2*>(&g_xh[i])     = __floats2half2_rn(v.x, v.y);
    *reinterpret_cast<__half2*>(&g_xh[i + 2]) = __floats2half2_rn(v.z, v.w);
}

__device__ __forceinline__ unsigned smem_u32(const void* p) {
    return (unsigned)__cvta_generic_to_shared(p);
}

__device__ __forceinline__ void ldsm_x4(unsigned& r0, unsigned& r1, unsigned& r2, unsigned& r3,
                                        unsigned addr) {
    asm volatile("ldmatrix.sync.aligned.m8n8.x4.shared.b16 {%0,%1,%2,%3}, [%4];\n"
                 : "=r"(r0), "=r"(r1), "=r"(r2), "=r"(r3)
                 : "r"(addr));
}

__device__ __forceinline__ void mma_16816(float& c0, float& c1, float& c2, float& c3,
                                          unsigned a0, unsigned a1, unsigned a2, unsigned a3,
                                          unsigned b0, unsigned b1) {
    asm volatile("mma.sync.aligned.m16n8k16.row.col.f32.f16.f16.f32 "
                 "{%0,%1,%2,%3}, {%4,%5,%6,%7}, {%8,%9}, {%0,%1,%2,%3};\n"
                 : "+f"(c0), "+f"(c1), "+f"(c2), "+f"(c3)
                 : "r"(a0), "r"(a1), "r"(a2), "r"(a3), "r"(b0), "r"(b1));
}

__device__ __forceinline__ void cp_async16(unsigned saddr, const void* gaddr) {
    asm volatile("cp.async.cg.shared.global [%0], [%1], 16;\n"
                 :: "r"(saddr), "l"(gaddr));
}

// q in [0,256): fp16x2 {1024+lo, 1024+hi} - 1032 (exact), * scale (one fp16 rounding).
__device__ __forceinline__ unsigned dequant(unsigned q, __half2 s2) {
    unsigned t = ((q | (q << 12)) | 0x64006400u) & 0x640F640Fu;
    __half2 th = *reinterpret_cast<__half2*>(&t);
    const unsigned offc = 0x64086408u;  // half2 {1032, 1032}
    __half2 off = *reinterpret_cast<const __half2*>(&offc);
    __half2 wv = __hmul2(__hsub2(th, off), s2);
    return *reinterpret_cast<unsigned*>(&wv);
}

__global__ __launch_bounds__(128, 3)
void int4_linear_kernel(const int* __restrict__ w,
                        const float* __restrict__ scales,
                        const float* __restrict__ bias,
                        float* __restrict__ out) {
    // xs: 64 rows x 64 halves (128B/row), XOR swizzle B ^= (row&7)<<4
    // ws: 32 rows x 64 ints  (256B/row), XOR swizzle col ^= (row&3)<<3
    __shared__ __half xs[NBUF][M_DIM * BK];          // 3 x 8192 B
    __shared__ int    ws[NBUF][(BK / 2) * BN];       // 3 x 8192 B   -> 48KB total

    const int tid  = threadIdx.x;
    const int lane = tid & 31;
    const int warp = tid >> 5;
    const int r    = lane & 3;    // kh sub-row within B fragment
    const int c    = lane >> 2;   // n sub-col within n8 tile
    const int nwarp = blockIdx.x * BN + warp * 16;
    const int col   = nwarp + c;
    const int wc    = warp * 16 + c;                 // column word index in CTA tile
    // swizzled per-thread weight column indices (row&3 == r for both frag halves)
    const int wcx0 = wc ^ (r << 3);
    const int wcx1 = (wc + 8) ^ (r << 3);

    float acc[4][2][4];
#pragma unroll
    for (int mi = 0; mi < 4; ++mi)
#pragma unroll
        for (int j = 0; j < 2; ++j)
#pragma unroll
            for (int f = 0; f < 4; ++f) acc[mi][j][f] = 0.0f;

    const int* wsrc = w + (size_t)blockIdx.x * BN;

    // stage copy: x tile (64x64 halves) + w tile (32x64 ints), one commit group
    auto copy_stage = [&](int g, int buf) {
#pragma unroll
        for (int i = 0; i < 4; ++i) {           // x: 512 chunks of 16B
            int idx = tid + i * 128;
            int row = idx >> 3;
            int cc  = idx & 7;
            unsigned boff = (unsigned)(row * 128 + cc * 16);
            boff ^= (unsigned)((row & 7) << 4);
            const __half* gp = g_xh + (size_t)row * K_DIM + (size_t)g * BK + cc * 8;
            cp_async16(smem_u32((const char*)&xs[buf][0] + boff), gp);
        }
#pragma unroll
        for (int i = 0; i < 4; ++i) {           // w: 512 chunks of 16B
            int idx = tid + i * 128;
            int row = idx >> 4;
            int cc  = idx & 15;
            int colw = (cc * 4) ^ ((row & 3) << 3);
            const int* gp = wsrc + (size_t)(g * (BK / 2) + row) * N_DIM + cc * 4;
            cp_async16(smem_u32(&ws[buf][row * BN + colw]), gp);
        }
        asm volatile("cp.async.commit_group;\n");
    };

    // fragment read from staged weights: step t covers packed rows t*8 .. t*8+7
    auto lds_w = [&](const int* wsb, int t, unsigned q[4]) {
        const int* p0 = wsb + (t * 8 + r) * BN;
        const int* p1 = p0 + 4 * BN;
        q[0] = (unsigned)p0[wcx0];
        q[1] = (unsigned)p0[wcx1];
        q[2] = (unsigned)p1[wcx0];
        q[3] = (unsigned)p1[wcx1];
    };

    // ldmatrix per-thread terms: row_l = lane&15, cb = (lane>>4)*16B, sw on bits 4-6
    const int row_l = lane & 15;
    const unsigned roff = (unsigned)(row_l * 128);
    const unsigned cb   = (unsigned)((lane >> 4) * 16);
    const unsigned sw   = (unsigned)((row_l & 7) << 4);
    const unsigned xs_base[NBUF] = { smem_u32(&xs[0][0]), smem_u32(&xs[1][0]),
                                     smem_u32(&xs[2][0]) };

    // prologue: 2 stages in flight
    copy_stage(0, 0);
    copy_stage(1, 1);

    float sraw[2];
#pragma unroll
    for (int j = 0; j < 2; ++j)
        sraw[j] = __ldg(scales + col + j * 8);   // group 0

    __half2 s2[2];

    for (int g = 0; g < NSTAGE; ++g) {
        if (g < NSTAGE - 1) asm volatile("cp.async.wait_group 1;\n");
        else                asm volatile("cp.async.wait_group 0;\n");
        __syncthreads();

        // refill pipe (overwrites buffer of stage g-1; safe after the barrier)
        if (g + 2 < NSTAGE) copy_stage(g + 2, (g + 2) % NBUF);

        if ((g & 1) == 0) {
#pragma unroll
            for (int j = 0; j < 2; ++j)
                s2[j] = __half2half2(__float2half_rn(sraw[j]));
            int gn = (g >> 1) + 1;
            if (gn > 63) gn = 63;
#pragma unroll
            for (int j = 0; j < 2; ++j)
                sraw[j] = __ldg(scales + (size_t)gn * N_DIM + col + j * 8);
        }

        const int buf = g % NBUF;
        const unsigned sbase = xs_base[buf];
        const int* wsb = &ws[buf][0];

        unsigned qc[4], qn[4];
        lds_w(wsb, 0, qc);

#pragma unroll
        for (int t = 0; t < 4; ++t) {
            if (t < 3) lds_w(wsb, t + 1, qn);   // prefetch next step's frags

            unsigned a[4][4];
#pragma unroll
            for (int mi = 0; mi < 4; ++mi) {
                unsigned addr = sbase + (unsigned)(mi * 2048) + roff +
                                (((unsigned)(t * 32) + cb) ^ sw);
                ldsm_x4(a[mi][0], a[mi][1], a[mi][2], a[mi][3], addr);
            }

#pragma unroll
            for (int j = 0; j < 2; ++j) {
                unsigned b0 = dequant(qc[j],     s2[j]);
                unsigned b1 = dequant(qc[2 + j], s2[j]);
#pragma unroll
                for (int mi = 0; mi < 4; ++mi)
                    mma_16816(acc[mi][j][0], acc[mi][j][1], acc[mi][j][2], acc[mi][j][3],
                              a[mi][0], a[mi][1], a[mi][2], a[mi][3], b0, b1);
            }
#pragma unroll
            for (int i = 0; i < 4; ++i) qc[i] = qn[i];
        }
    }

    // epilogue: fp32 acc -> fp16 round, + fp16 bias, upcast -> f32 store
#pragma unroll
    for (int mi = 0; mi < 4; ++mi) {
        int m0 = mi * 16 + (lane >> 2);
#pragma unroll
        for (int j = 0; j < 2; ++j) {
            int n = nwarp + j * 8 + 2 * (lane & 3);
            float2 bf = *reinterpret_cast<const float2*>(bias + n);
            __half2 bb = __floats2half2_rn(bf.x, bf.y);  // exact

            __half2 v0 = __halves2half2(__float2half_rn(acc[mi][j][0]),
                                        __float2half_rn(acc[mi][j][1]));
            v0 = __hadd2(v0, bb);
            float2 o0 = { __half2float(__low2half(v0)), __half2float(__high2half(v0)) };
            *reinterpret_cast<float2*>(out + (size_t)m0 * N_DIM + n) = o0;

            __half2 v1 = __halves2half2(__float2half_rn(acc[mi][j][2]),
                                        __float2half_rn(acc[mi][j][3]));
            v1 = __hadd2(v1, bb);
            float2 o1 = { __half2float(__low2half(v1)), __half2float(__high2half(v1)) };
            *reinterpret_cast<float2*>(out + (size_t)(m0 + 8) * N_DIM + n) = o1;
        }
    }
}

extern "C" void kernel_launch(void* const* d_in, const int* in_sizes, int n_in,
                              void* d_out, int out_size) {
    const float* x      = (const float*)d_in[0];
    const int*   w      = (const int*)d_in[1];
    const float* scales = (const float*)d_in[2];
    const float* bias   = (const float*)d_in[3];
    float*       out    = (float*)d_out;

    convert_x_kernel<<<(M_DIM * K_DIM / 4 + 255) / 256, 256>>>(x);

    dim3 grid(N_DIM / BN);   // 448 CTAs (~3 per SM, balanced)
    dim3 block(128);         // 4 warps x 16 columns
    int4_linear_kernel<<<grid, block>>>(w, scales, bias, out);
}

// round 10
// speedup vs baseline: 1.8726x; 1.0122x over previous
#include <cuda_runtime.h>
#include <cuda_fp16.h>
#include <cstdint>
#include <cstddef>

// INT4 packed linear: y[64, 28672] = x[64, 8192] @ dequant(w_packed, scales) + bias
// Harness canonicalizes fp16 tensors to float32 (lossless): x/scales/bias/out are f32.
// Math replicates reference: fp16 dequant ((nib-8)*s in fp16), fp32 MMA accum,
// fp16 rounding of y, fp16 bias add, upcast to f32 for the store.
//
// R10: depth-3 cp.async pipeline (NBUF=4, 64KB dynamic SMEM, wait_group 2),
//      XOR-swizzled buffers, 1 barrier/stage.

#define K_DIM   8192
#define N_DIM   28672
#define M_DIM   64
#define BN      64            // columns per CTA (4 warps x 16 cols)
#define BK      64            // k per stage (32 packed rows); scale-group = 2 stages
#define NSTAGE  (K_DIM / BK)  // 128 stages
#define NBUF    4
#define XS_ELEMS (M_DIM * BK)        // 4096 halves = 8KB per buffer
#define WS_ELEMS ((BK / 2) * BN)     // 2048 ints  = 8KB per buffer
#define SMEM_BYTES (NBUF * (XS_ELEMS * 2 + WS_ELEMS * 4))   // 64KB

// fp16 copy of x (scratch via __device__ global)
__device__ __align__(16) __half g_xh[M_DIM * K_DIM];

__global__ void convert_x_kernel(const float* __restrict__ xf) {
    int i = (blockIdx.x * blockDim.x + threadIdx.x) * 4;
    float4 v = *reinterpret_cast<const float4*>(xf + i);
    *reinterpret_cast<__half2*>(&g_xh[i])     = __floats2half2_rn(v.x, v.y);
    *reinterpret_cast<__half2*>(&g_xh[i + 2]) = __floats2half2_rn(v.z, v.w);
}

__device__ __forceinline__ unsigned smem_u32(const void* p) {
    return (unsigned)__cvta_generic_to_shared(p);
}

__device__ __forceinline__ void ldsm_x4(unsigned& r0, unsigned& r1, unsigned& r2, unsigned& r3,
                                        unsigned addr) {
    asm volatile("ldmatrix.sync.aligned.m8n8.x4.shared.b16 {%0,%1,%2,%3}, [%4];\n"
                 : "=r"(r0), "=r"(r1), "=r"(r2), "=r"(r3)
                 : "r"(addr));
}

__device__ __forceinline__ void mma_16816(float& c0, float& c1, float& c2, float& c3,
                                          unsigned a0, unsigned a1, unsigned a2, unsigned a3,
                                          unsigned b0, unsigned b1) {
    asm volatile("mma.sync.aligned.m16n8k16.row.col.f32.f16.f16.f32 "
                 "{%0,%1,%2,%3}, {%4,%5,%6,%7}, {%8,%9}, {%0,%1,%2,%3};\n"
                 : "+f"(c0), "+f"(c1), "+f"(c2), "+f"(c3)
                 : "r"(a0), "r"(a1), "r"(a2), "r"(a3), "r"(b0), "r"(b1));
}

__device__ __forceinline__ void cp_async16(unsigned saddr, const void* gaddr) {
    asm volatile("cp.async.cg.shared.global [%0], [%1], 16;\n"
                 :: "r"(saddr), "l"(gaddr));
}

// q in [0,256): fp16x2 {1024+lo, 1024+hi} - 1032 (exact), * scale (one fp16 rounding).
__device__ __forceinline__ unsigned dequant(unsigned q, __half2 s2) {
    unsigned t = ((q | (q << 12)) | 0x64006400u) & 0x640F640Fu;
    __half2 th = *reinterpret_cast<__half2*>(&t);
    const unsigned offc = 0x64086408u;  // half2 {1032, 1032}
    __half2 off = *reinterpret_cast<const __half2*>(&offc);
    __half2 wv = __hmul2(__hsub2(th, off), s2);
    return *reinterpret_cast<unsigned*>(&wv);
}

__global__ __launch_bounds__(128, 3)
void int4_linear_kernel(const int* __restrict__ w,
                        const float* __restrict__ scales,
                        const float* __restrict__ bias,
                        float* __restrict__ out) {
    // Dynamic SMEM: NBUF x { x tile 64x64 halves (swizzle B^=(row&7)<<4),
    //                        w tile 32x64 ints   (swizzle col^=(row&3)<<3) }
    extern __shared__ __align__(16) char smem_raw[];
    __half* xs_all = (__half*)smem_raw;                          // NBUF * 4096 halves
    int*    ws_all = (int*)(smem_raw + NBUF * XS_ELEMS * 2);     // NBUF * 2048 ints

    const int tid  = threadIdx.x;
    const int lane = tid & 31;
    const int warp = tid >> 5;
    const int r    = lane & 3;    // kh sub-row within B fragment
    const int c    = lane >> 2;   // n sub-col within n8 tile
    const int nwarp = blockIdx.x * BN + warp * 16;
    const int col   = nwarp + c;
    const int wc    = warp * 16 + c;                 // column word index in CTA tile
    const int wcx0 = wc ^ (r << 3);                  // swizzled frag columns
    const int wcx1 = (wc + 8) ^ (r << 3);

    float acc[4][2][4];
#pragma unroll
    for (int mi = 0; mi < 4; ++mi)
#pragma unroll
        for (int j = 0; j < 2; ++j)
#pragma unroll
            for (int f = 0; f < 4; ++f) acc[mi][j][f] = 0.0f;

    const int* wsrc = w + (size_t)blockIdx.x * BN;

    // stage copy: x tile (64x64 halves) + w tile (32x64 ints), one commit group
    auto copy_stage = [&](int g, int buf) {
        __half* xsb = xs_all + buf * XS_ELEMS;
        int*    wsb = ws_all + buf * WS_ELEMS;
#pragma unroll
        for (int i = 0; i < 4; ++i) {           // x: 512 chunks of 16B
            int idx = tid + i * 128;
            int row = idx >> 3;
            int cc  = idx & 7;
            unsigned boff = (unsigned)(row * 128 + cc * 16);
            boff ^= (unsigned)((row & 7) << 4);
            const __half* gp = g_xh + (size_t)row * K_DIM + (size_t)g * BK + cc * 8;
            cp_async16(smem_u32((const char*)xsb + boff), gp);
        }
#pragma unroll
        for (int i = 0; i < 4; ++i) {           // w: 512 chunks of 16B
            int idx = tid + i * 128;
            int row = idx >> 4;
            int cc  = idx & 15;
            int colw = (cc * 4) ^ ((row & 3) << 3);
            const int* gp = wsrc + (size_t)(g * (BK / 2) + row) * N_DIM + cc * 4;
            cp_async16(smem_u32(&wsb[row * BN + colw]), gp);
        }
        asm volatile("cp.async.commit_group;\n");
    };

    // fragment read from staged weights: step t covers packed rows t*8 .. t*8+7
    auto lds_w = [&](const int* wsb, int t, unsigned q[4]) {
        const int* p0 = wsb + (t * 8 + r) * BN;
        const int* p1 = p0 + 4 * BN;
        q[0] = (unsigned)p0[wcx0];
        q[1] = (unsigned)p0[wcx1];
        q[2] = (unsigned)p1[wcx0];
        q[3] = (unsigned)p1[wcx1];
    };

    // ldmatrix per-thread terms
    const int row_l = lane & 15;
    const unsigned roff = (unsigned)(row_l * 128);
    const unsigned cb   = (unsigned)((lane >> 4) * 16);
    const unsigned sw   = (unsigned)((row_l & 7) << 4);
    unsigned xs_base[NBUF];
#pragma unroll
    for (int i = 0; i < NBUF; ++i) xs_base[i] = smem_u32(xs_all + i * XS_ELEMS);

    // prologue: 3 stages in flight
    copy_stage(0, 0);
    copy_stage(1, 1);
    copy_stage(2, 2);

    float sraw[2];
#pragma unroll
    for (int j = 0; j < 2; ++j)
        sraw[j] = __ldg(scales + col + j * 8);   // group 0

    __half2 s2[2];

    for (int g = 0; g < NSTAGE; ++g) {
        // ensure stage g's group has landed (exact tail handling)
        if (g < NSTAGE - 2)      asm volatile("cp.async.wait_group 2;\n");
        else if (g == NSTAGE - 2) asm volatile("cp.async.wait_group 1;\n");
        else                      asm volatile("cp.async.wait_group 0;\n");
        __syncthreads();

        // refill pipe (overwrites buffer of stage g-1; safe after the barrier)
        if (g + 3 < NSTAGE) copy_stage(g + 3, (g + 3) % NBUF);

        if ((g & 1) == 0) {
#pragma unroll
            for (int j = 0; j < 2; ++j)
                s2[j] = __half2half2(__float2half_rn(sraw[j]));
            int gn = (g >> 1) + 1;
            if (gn > 63) gn = 63;
#pragma unroll
            for (int j = 0; j < 2; ++j)
                sraw[j] = __ldg(scales + (size_t)gn * N_DIM + col + j * 8);
        }

        const int buf = g % NBUF;
        const unsigned sbase = xs_base[buf];
        const int* wsb = ws_all + buf * WS_ELEMS;

        unsigned qc[4], qn[4];
        lds_w(wsb, 0, qc);

#pragma unroll
        for (int t = 0; t < 4; ++t) {
            if (t < 3) lds_w(wsb, t + 1, qn);   // prefetch next step's frags

            unsigned a[4][4];
#pragma unroll
            for (int mi = 0; mi < 4; ++mi) {
                unsigned addr = sbase + (unsigned)(mi * 2048) + roff +
                                (((unsigned)(t * 32) + cb) ^ sw);
                ldsm_x4(a[mi][0], a[mi][1], a[mi][2], a[mi][3], addr);
            }

#pragma unroll
            for (int j = 0; j < 2; ++j) {
                unsigned b0 = dequant(qc[j],     s2[j]);
                unsigned b1 = dequant(qc[2 + j], s2[j]);
#pragma unroll
                for (int mi = 0; mi < 4; ++mi)
                    mma_16816(acc[mi][j][0], acc[mi][j][1], acc[mi][j][2], acc[mi][j][3],
                              a[mi][0], a[mi][1], a[mi][2], a[mi][3], b0, b1);
            }
#pragma unroll
            for (int i = 0; i < 4; ++i) qc[i] = qn[i];
        }
    }

    // epilogue: fp32 acc -> fp16 round, + fp16 bias, upcast -> f32 store
#pragma unroll
    for (int mi = 0; mi < 4; ++mi) {
        int m0 = mi * 16 + (lane >> 2);
#pragma unroll
        for (int j = 0; j < 2; ++j) {
            int n = nwarp + j * 8 + 2 * (lane & 3);
            float2 bf = *reinterpret_cast<const float2*>(bias + n);
            __half2 bb = __floats2half2_rn(bf.x, bf.y);  // exact

            __half2 v0 = __halves2half2(__float2half_rn(acc[mi][j][0]),
                                        __float2half_rn(acc[mi][j][1]));
            v0 = __hadd2(v0, bb);
            float2 o0 = { __half2float(__low2half(v0)), __half2float(__high2half(v0)) };
            *reinterpret_cast<float2*>(out + (size_t)m0 * N_DIM + n) = o0;

            __half2 v1 = __halves2half2(__float2half_rn(acc[mi][j][2]),
                                        __float2half_rn(acc[mi][j][3]));
            v1 = __hadd2(v1, bb);
            float2 o1 = { __half2float(__low2half(v1)), __half2float(__high2half(v1)) };
            *reinterpret_cast<float2*>(out + (size_t)(m0 + 8) * N_DIM + n) = o1;
        }
    }
}

extern "C" void kernel_launch(void* const* d_in, const int* in_sizes, int n_in,
                              void* d_out, int out_size) {
    const float* x      = (const float*)d_in[0];
    const int*   w      = (const int*)d_in[1];
    const float* scales = (const float*)d_in[2];
    const float* bias   = (const float*)d_in[3];
    float*       out    = (float*)d_out;

    // opt-in to 64KB dynamic SMEM (idempotent; attribute set, not an allocation)
    cudaFuncSetAttribute(int4_linear_kernel,
                         cudaFuncAttributeMaxDynamicSharedMemorySize, SMEM_BYTES);

    convert_x_kernel<<<(M_DIM * K_DIM / 4 + 255) / 256, 256>>>(x);

    dim3 grid(N_DIM / BN);   // 448 CTAs (~3 per SM, balanced)
    dim3 block(128);         // 4 warps x 16 columns
    int4_linear_kernel<<<grid, block, SMEM_BYTES>>>(w, scales, bias, out);
}